// round 5
// baseline (speedup 1.0000x reference)
#include <cuda_runtime.h>

// TinyGRU: B=4096 sequences, S=2048 steps, I=3, H=4, O=2.
// One thread per batch row; hidden state + all weights register-resident.
// f32x2 packed math for the gate GEMVs; MUFU.TANH for r/z sigmoids
// (0.5 pre-folded into weights/biases), accurate EX2+RCP tanh for n.

typedef unsigned long long u64;

constexpr int B_ = 4096, S_ = 2048, I_ = 3, H_ = 4, O_ = 2;

__device__ __forceinline__ u64 pk(float lo, float hi) {
    u64 r; asm("mov.b64 %0, {%1, %2};" : "=l"(r) : "f"(lo), "f"(hi)); return r;
}
__device__ __forceinline__ void upk(float& lo, float& hi, u64 v) {
    asm("mov.b64 {%0, %1}, %2;" : "=f"(lo), "=f"(hi) : "l"(v));
}
__device__ __forceinline__ u64 ffma2(u64 a, u64 b, u64 c) {
    u64 d; asm("fma.rn.f32x2 %0, %1, %2, %3;" : "=l"(d) : "l"(a), "l"(b), "l"(c)); return d;
}
__device__ __forceinline__ u64 fadd2(u64 a, u64 b) {
    u64 d; asm("add.rn.f32x2 %0, %1, %2;" : "=l"(d) : "l"(a), "l"(b)); return d;
}
__device__ __forceinline__ u64 fmul2(u64 a, u64 b) {
    u64 d; asm("mul.rn.f32x2 %0, %1, %2;" : "=l"(d) : "l"(a), "l"(b)); return d;
}
__device__ __forceinline__ float tanha(float x) {
    float y; asm("tanh.approx.f32 %0, %1;" : "=f"(y) : "f"(x)); return y;
}
__device__ __forceinline__ float ex2a(float x) {
    float y; asm("ex2.approx.f32 %0, %1;" : "=f"(y) : "f"(x)); return y;
}
__device__ __forceinline__ float rcpa(float x) {
    float y; asm("rcp.approx.f32 %0, %1;" : "=f"(y) : "f"(x)); return y;
}

__global__ void __launch_bounds__(32, 1) tinygru_kernel(
    const float* __restrict__ inputs,   // [B, S, I]
    const float* __restrict__ W_ih,     // [12, 3]  rows: r0..3, z0..3, n0..3
    const float* __restrict__ W_hh,     // [12, 4]
    const float* __restrict__ b_ih,     // [12]
    const float* __restrict__ b_hh,     // [12]
    const float* __restrict__ W_ro,     // [2, 4]
    const float* __restrict__ b_ro,     // [2]
    const float* __restrict__ h0,       // [1, 4]
    float* __restrict__ out)            // [B*S*O] then [B*H]
{
    const int b = blockIdx.x * blockDim.x + threadIdx.x;
    if (b >= B_) return;

    // ---- Pack weights into f32x2 pairs (gate pairs 2p, 2p+1). ----
    // Pairs p=0,1 -> r gates; p=2,3 -> z gates; p=4,5 -> n gates.
    // r/z rows pre-scaled by 0.5 (sigmoid via tanh identity); r/z h-bias
    // folded into the x-bias so hg for r/z starts at zero.
    u64 Wx0[6], Wx1[6], Wx2[6], BxP[6];
    u64 Wh0[6], Wh1[6], Wh2[6], Wh3[6];
    u64 Bhn[2], Wro[4], Bro;

    #pragma unroll
    for (int p = 0; p < 6; ++p) {
        const int g0 = 2 * p, g1 = g0 + 1;
        const float s = (p < 4) ? 0.5f : 1.0f;
        Wx0[p] = pk(s * W_ih[g0 * 3 + 0], s * W_ih[g1 * 3 + 0]);
        Wx1[p] = pk(s * W_ih[g0 * 3 + 1], s * W_ih[g1 * 3 + 1]);
        Wx2[p] = pk(s * W_ih[g0 * 3 + 2], s * W_ih[g1 * 3 + 2]);
        Wh0[p] = pk(s * W_hh[g0 * 4 + 0], s * W_hh[g1 * 4 + 0]);
        Wh1[p] = pk(s * W_hh[g0 * 4 + 1], s * W_hh[g1 * 4 + 1]);
        Wh2[p] = pk(s * W_hh[g0 * 4 + 2], s * W_hh[g1 * 4 + 2]);
        Wh3[p] = pk(s * W_hh[g0 * 4 + 3], s * W_hh[g1 * 4 + 3]);
        if (p < 4)
            BxP[p] = pk(0.5f * (b_ih[g0] + b_hh[g0]),
                        0.5f * (b_ih[g1] + b_hh[g1]));
        else
            BxP[p] = pk(b_ih[g0], b_ih[g1]);
    }
    Bhn[0] = pk(b_hh[8], b_hh[9]);
    Bhn[1] = pk(b_hh[10], b_hh[11]);
    #pragma unroll
    for (int j = 0; j < 4; ++j)
        Wro[j] = pk(W_ro[j], W_ro[4 + j]);   // (W_ro[0][j], W_ro[1][j])
    Bro = pk(b_ro[0], b_ro[1]);

    const u64 HALF2 = pk(0.5f, 0.5f);
    const u64 NEG1  = pk(-1.0f, -1.0f);
    const float C2L2E = 2.8853900817779268f;   // 2*log2(e)

    // ---- Hidden state (packed pairs + per-component broadcasts). ----
    float hv0 = h0[0], hv1 = h0[1], hv2 = h0[2], hv3 = h0[3];
    u64 h01 = pk(hv0, hv1), h23 = pk(hv2, hv3);
    u64 hb0 = pk(hv0, hv0), hb1 = pk(hv1, hv1);
    u64 hb2 = pk(hv2, hv2), hb3 = pk(hv3, hv3);

    const float4* __restrict__ xp =
        reinterpret_cast<const float4*>(inputs + (size_t)b * (S_ * I_));
    float* __restrict__ op = out + (size_t)b * (S_ * O_);

    // One 4-step group = 12 floats = 3x float4; prefetch one group ahead.
    float4 A0 = xp[0], A1 = xp[1], A2 = xp[2];

    constexpr int NG = S_ / 4;   // 512 groups
    #pragma unroll 1
    for (int g = 0; g < NG; ++g) {
        const int gn = (g + 1 < NG) ? (g + 1) : g;
        const float4 P0 = xp[3 * gn + 0];
        const float4 P1 = xp[3 * gn + 1];
        const float4 P2 = xp[3 * gn + 2];

        const float xs[12] = {A0.x, A0.y, A0.z, A0.w,
                              A1.x, A1.y, A1.z, A1.w,
                              A2.x, A2.y, A2.z, A2.w};

        #pragma unroll
        for (int k = 0; k < 4; ++k) {
            // x broadcast pairs
            const u64 xx0 = pk(xs[3 * k + 0], xs[3 * k + 0]);
            const u64 xx1 = pk(xs[3 * k + 1], xs[3 * k + 1]);
            const u64 xx2 = pk(xs[3 * k + 2], xs[3 * k + 2]);

            // x-gates: 18 FFMA2 (independent of h -> fills latency slack)
            u64 xg[6];
            #pragma unroll
            for (int p = 0; p < 6; ++p) {
                u64 a = ffma2(Wx0[p], xx0, BxP[p]);
                a = ffma2(Wx1[p], xx1, a);
                xg[p] = ffma2(Wx2[p], xx2, a);
            }

            // h-gates: 24 FFMA2 (r/z rows pre-scaled 0.5, bias folded away)
            u64 hg[6];
            #pragma unroll
            for (int p = 0; p < 6; ++p) {
                u64 a = (p < 4) ? fmul2(Wh0[p], hb0)
                                : ffma2(Wh0[p], hb0, Bhn[p - 4]);
                a = ffma2(Wh1[p], hb1, a);
                a = ffma2(Wh2[p], hb2, a);
                hg[p] = ffma2(Wh3[p], hb3, a);
            }

            // r, z via sigma(x) = 0.5 + 0.5*tanh(x/2); args already halved
            float t0, t1, t2, t3, t4, t5, t6, t7;
            { u64 a = fadd2(xg[0], hg[0]); upk(t0, t1, a); }
            { u64 a = fadd2(xg[1], hg[1]); upk(t2, t3, a); }
            { u64 a = fadd2(xg[2], hg[2]); upk(t4, t5, a); }
            { u64 a = fadd2(xg[3], hg[3]); upk(t6, t7, a); }
            t0 = tanha(t0); t1 = tanha(t1); t2 = tanha(t2); t3 = tanha(t3);
            t4 = tanha(t4); t5 = tanha(t5); t6 = tanha(t6); t7 = tanha(t7);
            const u64 r01 = ffma2(pk(t0, t1), HALF2, HALF2);
            const u64 r23 = ffma2(pk(t2, t3), HALF2, HALF2);
            const u64 z01 = ffma2(pk(t4, t5), HALF2, HALF2);
            const u64 z23 = ffma2(pk(t6, t7), HALF2, HALF2);

            // n = tanh(xn + r*hn), accurate: tanh(u) = 1 - 2/(1 + e^{2u})
            const u64 uu01 = ffma2(r01, hg[4], xg[4]);
            const u64 uu23 = ffma2(r23, hg[5], xg[5]);
            float u0, u1, u2, u3;
            upk(u0, u1, uu01); upk(u2, u3, uu23);
            const float e0 = ex2a(u0 * C2L2E);
            const float e1 = ex2a(u1 * C2L2E);
            const float e2 = ex2a(u2 * C2L2E);
            const float e3 = ex2a(u3 * C2L2E);
            const float n0 = fmaf(rcpa(e0 + 1.0f), -2.0f, 1.0f);
            const float n1 = fmaf(rcpa(e1 + 1.0f), -2.0f, 1.0f);
            const float n2 = fmaf(rcpa(e2 + 1.0f), -2.0f, 1.0f);
            const float n3 = fmaf(rcpa(e3 + 1.0f), -2.0f, 1.0f);
            const u64 n01 = pk(n0, n1), n23 = pk(n2, n3);

            // h = n + z*(h - n)
            const u64 d01 = ffma2(n01, NEG1, h01);
            const u64 d23 = ffma2(n23, NEG1, h23);
            h01 = ffma2(z01, d01, n01);
            h23 = ffma2(z23, d23, n23);
            upk(hv0, hv1, h01); upk(hv2, hv3, h23);
            hb0 = pk(hv0, hv0); hb1 = pk(hv1, hv1);
            hb2 = pk(hv2, hv2); hb3 = pk(hv3, hv3);

            // readout: o = W_ro @ h + b_ro  (packed (o0,o1))
            u64 o = ffma2(Wro[0], hb0, Bro);
            o = ffma2(Wro[1], hb1, o);
            o = ffma2(Wro[2], hb2, o);
            o = ffma2(Wro[3], hb3, o);
            *reinterpret_cast<u64*>(op) = o;   // 8B store, 8B-aligned
            op += 2;
        }

        A0 = P0; A1 = P1; A2 = P2;
    }

    // h_final: after the outputs block
    u64* hf = reinterpret_cast<u64*>(out + (size_t)B_ * S_ * O_) + (size_t)b * 2;
    hf[0] = h01;
    hf[1] = h23;
}

extern "C" void kernel_launch(void* const* d_in, const int* in_sizes, int n_in,
                              void* d_out, int out_size) {
    (void)in_sizes; (void)n_in; (void)out_size;
    const float* inputs = (const float*)d_in[0];
    const float* W_ih   = (const float*)d_in[1];
    const float* W_hh   = (const float*)d_in[2];
    const float* b_ih   = (const float*)d_in[3];
    const float* b_hh   = (const float*)d_in[4];
    const float* W_ro   = (const float*)d_in[5];
    const float* b_ro   = (const float*)d_in[6];
    const float* h0     = (const float*)d_in[7];
    float* out = (float*)d_out;

    // 4096 threads = 128 one-warp blocks -> one warp per SM (no SMSP sharing)
    tinygru_kernel<<<B_ / 32, 32>>>(inputs, W_ih, W_hh, b_ih, b_hh,
                                    W_ro, b_ro, h0, out);
}

// round 8
// speedup vs baseline: 1.4320x; 1.4320x over previous
#include <cuda_runtime.h>

// TinyGRU: B=4096, S=2048, I=3, H=4, O=2.
// Two lanes per batch row (lane l and l^16 in the same warp), each owning 2 of
// the 4 hidden components. SIMT-uniform via role-permuted register weights;
// per-step cross-lane traffic = 2 shfl.xor of f32 (the h-halves exchange).
// sigma via tanh.approx with 0.5 folded into weights; n via tanh.approx with
// the r-fold uu = (xn + hg_n) + t_r*hg_n (0.5 folded into W_hh_n rows);
// h-update via h' = 0.5(h+n) + t_z*0.5(h-n) (no z materialization).

typedef unsigned long long u64;

constexpr int B_ = 4096, S_ = 2048, I_ = 3, H_ = 4, O_ = 2;

__device__ __forceinline__ u64 pk(float lo, float hi) {
    u64 r; asm("mov.b64 %0, {%1, %2};" : "=l"(r) : "f"(lo), "f"(hi)); return r;
}
__device__ __forceinline__ void upk(float& lo, float& hi, u64 v) {
    asm("mov.b64 {%0, %1}, %2;" : "=f"(lo), "=f"(hi) : "l"(v));
}
__device__ __forceinline__ u64 ffma2(u64 a, u64 b, u64 c) {
    u64 d; asm("fma.rn.f32x2 %0, %1, %2, %3;" : "=l"(d) : "l"(a), "l"(b), "l"(c)); return d;
}
__device__ __forceinline__ u64 fadd2(u64 a, u64 b) {
    u64 d; asm("add.rn.f32x2 %0, %1, %2;" : "=l"(d) : "l"(a), "l"(b)); return d;
}
__device__ __forceinline__ u64 fmul2(u64 a, u64 b) {
    u64 d; asm("mul.rn.f32x2 %0, %1, %2;" : "=l"(d) : "l"(a), "l"(b)); return d;
}
__device__ __forceinline__ float tanha(float x) {
    float y; asm("tanh.approx.f32 %0, %1;" : "=f"(y) : "f"(x)); return y;
}

__global__ void __launch_bounds__(32, 1) tinygru_kernel(
    const float* __restrict__ inputs,   // [B, S, I]
    const float* __restrict__ W_ih,     // [12, 3]  rows: r0..3, z0..3, n0..3
    const float* __restrict__ W_hh,     // [12, 4]
    const float* __restrict__ b_ih,     // [12]
    const float* __restrict__ b_hh,     // [12]
    const float* __restrict__ W_ro,     // [2, 4]
    const float* __restrict__ b_ro,     // [2]
    const float* __restrict__ h0,       // [1, 4]
    float* __restrict__ out)            // [B*S*O] then [B*H]
{
    const int lane = threadIdx.x & 31;
    const int role = lane >> 4;                 // 0 -> h comps {0,1}; 1 -> {2,3}
    const int row  = blockIdx.x * 16 + (lane & 15);

    const int j0 = 2 * role, j1 = j0 + 1;       // own components
    const int k0 = 2 - j0,   k1 = k0 + 1;       // partner components

    // ---- Per-lane packed weights. Gates q: 0=r, 1=z, 2=n; row = q*4 + comp.
    // W_hh scaled by 0.5 for ALL gates (sigmoid-half for r/z; uu-fold for n).
    // W_ih scaled 0.5 for r/z only. Biases:
    //   r/z: Bx = 0.5*(b_ih+b_hh), Bh = 0
    //   n:   Bx = b_ih,            Bh = 0.5*b_hh
    u64 Wx[3][3], Who[3][2], Whx[3][2], Bx[3], Bh[3];
    #pragma unroll
    for (int q = 0; q < 3; ++q) {
        const int r0 = q * 4 + j0, r1 = q * 4 + j1;
        const float si = (q < 2) ? 0.5f : 1.0f;
        #pragma unroll
        for (int i = 0; i < 3; ++i)
            Wx[q][i] = pk(si * W_ih[r0 * 3 + i], si * W_ih[r1 * 3 + i]);
        Who[q][0] = pk(0.5f * W_hh[r0 * 4 + j0], 0.5f * W_hh[r1 * 4 + j0]);
        Who[q][1] = pk(0.5f * W_hh[r0 * 4 + j1], 0.5f * W_hh[r1 * 4 + j1]);
        Whx[q][0] = pk(0.5f * W_hh[r0 * 4 + k0], 0.5f * W_hh[r1 * 4 + k0]);
        Whx[q][1] = pk(0.5f * W_hh[r0 * 4 + k1], 0.5f * W_hh[r1 * 4 + k1]);
        if (q < 2) {
            Bx[q] = pk(0.5f * (b_ih[r0] + b_hh[r0]),
                       0.5f * (b_ih[r1] + b_hh[r1]));
            Bh[q] = pk(0.0f, 0.0f);
        } else {
            Bx[q] = pk(b_ih[r0], b_ih[r1]);
            Bh[q] = pk(0.5f * b_hh[r0], 0.5f * b_hh[r1]);
        }
    }
    const u64 WroA = pk(W_ro[j0], W_ro[4 + j0]);
    const u64 WroB = pk(W_ro[j1], W_ro[4 + j1]);
    const u64 WroC = pk(W_ro[k0], W_ro[4 + k0]);
    const u64 WroD = pk(W_ro[k1], W_ro[4 + k1]);
    const u64 Bro  = pk(b_ro[0], b_ro[1]);
    const u64 HALF = pk(0.5f, 0.5f), NEGH = pk(-0.5f, -0.5f);

    // ---- State: own packed pair + broadcast pairs of all 4 components.
    u64 h_own = pk(h0[j0], h0[j1]);
    u64 hbA = pk(h0[j0], h0[j0]), hbB = pk(h0[j1], h0[j1]);
    u64 hbC = pk(h0[k0], h0[k0]), hbD = pk(h0[k1], h0[k1]);

    const float4* __restrict__ xp =
        reinterpret_cast<const float4*>(inputs + (size_t)row * (S_ * I_));
    float* __restrict__ op = out + (size_t)row * (S_ * O_);

    // 4 steps = 12 floats = 3x float4; prefetch one group ahead.
    float4 A0 = xp[0], A1 = xp[1], A2 = xp[2];

    constexpr int NG = S_ / 4;
    #pragma unroll 1
    for (int g = 0; g < NG; ++g) {
        const int gn = (g + 1 < NG) ? (g + 1) : g;
        const float4 P0 = xp[3 * gn + 0];
        const float4 P1 = xp[3 * gn + 1];
        const float4 P2 = xp[3 * gn + 2];

        const float xs[12] = {A0.x, A0.y, A0.z, A0.w,
                              A1.x, A1.y, A1.z, A1.w,
                              A2.x, A2.y, A2.z, A2.w};

        #pragma unroll
        for (int k = 0; k < 4; ++k) {
            const u64 xx0 = pk(xs[3 * k + 0], xs[3 * k + 0]);
            const u64 xx1 = pk(xs[3 * k + 1], xs[3 * k + 1]);
            const u64 xx2 = pk(xs[3 * k + 2], xs[3 * k + 2]);

            // x-gates (3 FFMA2 each) and h-gates (4 FFMA2 each), 3 pairs
            u64 xg[3], hg[3];
            #pragma unroll
            for (int q = 0; q < 3; ++q) {
                u64 a = ffma2(Wx[q][0], xx0, Bx[q]);
                a = ffma2(Wx[q][1], xx1, a);
                xg[q] = ffma2(Wx[q][2], xx2, a);
                u64 h = ffma2(Who[q][0], hbA, Bh[q]);
                h = ffma2(Who[q][1], hbB, h);
                h = ffma2(Whx[q][0], hbC, h);
                hg[q] = ffma2(Whx[q][1], hbD, h);
            }

            // r/z tanh of the (pre-halved) gate args
            float t0, t1, t2, t3;
            { const u64 a = fadd2(xg[0], hg[0]); upk(t0, t1, a); }
            { const u64 a = fadd2(xg[1], hg[1]); upk(t2, t3, a); }
            t0 = tanha(t0); t1 = tanha(t1);
            t2 = tanha(t2); t3 = tanha(t3);

            // n = tanh(xn + r*hn) with r folded: uu = (xn + hg_n) + t_r*hg_n
            const u64 nu = fadd2(xg[2], hg[2]);
            const u64 uu = ffma2(pk(t0, t1), hg[2], nu);
            float u0, u1; upk(u0, u1, uu);
            const u64 n = pk(tanha(u0), tanha(u1));

            // h' = 0.5(h+n) + t_z*0.5(h-n)   (own pair only)
            const u64 s  = fmul2(h_own, HALF);
            const u64 aa = ffma2(n, HALF, s);
            const u64 bb = ffma2(n, NEGH, s);
            h_own = ffma2(pk(t2, t3), bb, aa);

            // exchange halves with partner lane, rebuild broadcasts
            float hvA, hvB; upk(hvA, hvB, h_own);
            const float hvC = __shfl_xor_sync(0xffffffffu, hvA, 16);
            const float hvD = __shfl_xor_sync(0xffffffffu, hvB, 16);
            hbA = pk(hvA, hvA); hbB = pk(hvB, hvB);
            hbC = pk(hvC, hvC); hbD = pk(hvD, hvD);

            // readout on the new state (both lanes compute; role 0 stores)
            u64 o = ffma2(WroA, hbA, Bro);
            o = ffma2(WroB, hbB, o);
            o = ffma2(WroC, hbC, o);
            o = ffma2(WroD, hbD, o);
            if (role == 0) *reinterpret_cast<u64*>(op) = o;
            op += 2;
        }

        A0 = P0; A1 = P1; A2 = P2;
    }

    // h_final [B, H]: each lane stores its own pair at columns (j0, j1)
    u64* hf = reinterpret_cast<u64*>(out + (size_t)B_ * S_ * O_ +
                                     (size_t)row * H_ + j0);
    *hf = h_own;
}

extern "C" void kernel_launch(void* const* d_in, const int* in_sizes, int n_in,
                              void* d_out, int out_size) {
    (void)in_sizes; (void)n_in; (void)out_size;
    const float* inputs = (const float*)d_in[0];
    const float* W_ih   = (const float*)d_in[1];
    const float* W_hh   = (const float*)d_in[2];
    const float* b_ih   = (const float*)d_in[3];
    const float* b_hh   = (const float*)d_in[4];
    const float* W_ro   = (const float*)d_in[5];
    const float* b_ro   = (const float*)d_in[6];
    const float* h0     = (const float*)d_in[7];
    float* out = (float*)d_out;

    // 8192 threads = 256 one-warp blocks; 16 rows per warp, 2 lanes per row.
    tinygru_kernel<<<B_ * 2 / 32, 32>>>(inputs, W_ih, W_hh, b_ih, b_hh,
                                        W_ro, b_ro, h0, out);
}